// round 3
// baseline (speedup 1.0000x reference)
#include <cuda_runtime.h>
#include <cstdint>

// ---------------------------------------------------------------------------
// Problem constants
// ---------------------------------------------------------------------------
#define BATCH   1568
#define NTOK    64
#define CDIM    512
#define HEADS   16
#define HD      32
#define NW      49
#define MTOT    (BATCH * NTOK)          // 100352
#define QKVN    (3 * CDIM)              // 1536

// ---------------------------------------------------------------------------
// Device scratch (static globals: allocation-free per harness rules)
// ---------------------------------------------------------------------------
__device__ float g_qkv[(size_t)MTOT * QKVN];    // 616 MB: qkv projection output
__device__ float g_att[(size_t)MTOT * CDIM];    // 205 MB: attention output (B,N,C)
__device__ float g_bias[HEADS * NTOK * NTOK];   // (16,64,64) CRPB bias
__device__ float g_tbl[225 * HEADS];            // CRPB table (2W-1)^2 x H
__device__ float g_scale[HEADS];                // clamped temperature per head

// ---------------------------------------------------------------------------
// Kernel 1a: CRPB MLP table + temperature scale
// 225 entries; each thread does 384-hidden MLP -> 16 outputs.
// ---------------------------------------------------------------------------
__global__ void crpb_tbl_kernel(const float* __restrict__ ct,
                                const float* __restrict__ w1,
                                const float* __restrict__ b1,
                                const float* __restrict__ w2,
                                const float* __restrict__ ts)
{
    int e = threadIdx.x;
    if (e < HEADS) {
        // exp(min(t_scale, ln(100)))
        g_scale[e] = expf(fminf(ts[e], 4.6051701859880913680f));
    }
    if (e < 225) {
        float c0 = ct[e * 2 + 0];
        float c1 = ct[e * 2 + 1];
        float acc[HEADS];
#pragma unroll
        for (int h = 0; h < HEADS; h++) acc[h] = 0.f;
        for (int j = 0; j < 384; j++) {
            float hv = fmaxf(w1[j * 2 + 0] * c0 + w1[j * 2 + 1] * c1 + b1[j], 0.f);
#pragma unroll
            for (int h = 0; h < HEADS; h++) acc[h] += w2[h * 384 + j] * hv;
        }
#pragma unroll
        for (int h = 0; h < HEADS; h++) g_tbl[e * HEADS + h] = acc[h];
    }
}

// ---------------------------------------------------------------------------
// Kernel 1b: bias[h][i][j] = 16*sigmoid(tbl[rel_index[i][j]][h])
// ---------------------------------------------------------------------------
__global__ void bias_fill_kernel(const int* __restrict__ ridx)
{
    int t = blockIdx.x * blockDim.x + threadIdx.x;
    if (t >= HEADS * NTOK * NTOK) return;
    int h  = t >> 12;          // / 4096
    int ij = t & 4095;
    float v = g_tbl[ridx[ij] * HEADS + h];
    g_bias[t] = 16.f / (1.f + __expf(-v));
}

// ---------------------------------------------------------------------------
// Kernel 2/4: tiled fp32 GEMM  C[m][n] = sum_k A[m][k]*B[n][k] + bias[n]
// A: MxK row-major, B: NxK row-major (i.e. C = A @ B^T).
// 128x128 block tile, K-tile 16, 256 threads, 8x8 per thread.
// M % 128 == 0, N % 128 == 0, K % 16 == 0 (true for all our shapes).
// ---------------------------------------------------------------------------
#define BM 128
#define BN 128
#define BK 16

__global__ __launch_bounds__(256, 2)
void gemm_abT_kernel(const float* __restrict__ A, const float* __restrict__ B,
                     const float* __restrict__ bias, float* __restrict__ C,
                     int M, int N, int K)
{
    __shared__ float As[BK][BM + 4];
    __shared__ float Bs[BK][BN + 4];

    const int bm  = blockIdx.y * BM;
    const int bn  = blockIdx.x * BN;
    const int tid = threadIdx.x;
    const int tx  = tid & 15;
    const int ty  = tid >> 4;

    float acc[8][8];
#pragma unroll
    for (int i = 0; i < 8; i++)
#pragma unroll
        for (int j = 0; j < 8; j++) acc[i][j] = 0.f;

    for (int k0 = 0; k0 < K; k0 += BK) {
#pragma unroll
        for (int l = 0; l < 2; l++) {
            int f   = tid + l * 256;     // 0..511
            int row = f >> 2;            // 0..127
            int kv  = (f & 3) * 4;       // 0,4,8,12
            float4 va = *(const float4*)(A + (size_t)(bm + row) * K + k0 + kv);
            As[kv + 0][row] = va.x; As[kv + 1][row] = va.y;
            As[kv + 2][row] = va.z; As[kv + 3][row] = va.w;
            float4 vb = *(const float4*)(B + (size_t)(bn + row) * K + k0 + kv);
            Bs[kv + 0][row] = vb.x; Bs[kv + 1][row] = vb.y;
            Bs[kv + 2][row] = vb.z; Bs[kv + 3][row] = vb.w;
        }
        __syncthreads();

#pragma unroll
        for (int kk = 0; kk < BK; kk++) {
            float a[8], b[8];
#pragma unroll
            for (int i = 0; i < 8; i++) a[i] = As[kk][ty * 8 + i];
#pragma unroll
            for (int j = 0; j < 8; j++) b[j] = Bs[kk][tx * 8 + j];
#pragma unroll
            for (int i = 0; i < 8; i++)
#pragma unroll
                for (int j = 0; j < 8; j++) acc[i][j] += a[i] * b[j];
        }
        __syncthreads();
    }

#pragma unroll
    for (int i = 0; i < 8; i++) {
        int m = bm + ty * 8 + i;
#pragma unroll
        for (int j = 0; j < 8; j += 4) {
            int n = bn + tx * 8 + j;
            float4 o;
            o.x = acc[i][j + 0] + bias[n + 0];
            o.y = acc[i][j + 1] + bias[n + 1];
            o.z = acc[i][j + 2] + bias[n + 2];
            o.w = acc[i][j + 3] + bias[n + 3];
            *(float4*)(C + (size_t)m * N + n) = o;
        }
    }
}

// ---------------------------------------------------------------------------
// Kernel 3: attention. One block per (window b, head h).
// Loads Q/K/V 64x32 from g_qkv, cosine-normalizes Q,K rows, computes
// S = scale*Qn Kn^T + bias[h] + mask[b%49], row softmax, O = S V,
// writes O to g_att in (B, N, C) layout at column h*32.
// ---------------------------------------------------------------------------
__global__ __launch_bounds__(256, 4)
void attn_kernel(const float* __restrict__ mask, float* __restrict__ out)
{
    const int bh = blockIdx.x;
    const int b  = bh >> 4;          // / HEADS
    const int h  = bh & 15;
    const int w  = b % NW;

    __shared__ float Qs[64][33];
    __shared__ float Ks[64][33];
    __shared__ float Vs[64][33];
    __shared__ float Ss[64][65];

    const int tid = threadIdx.x;
    const float* base = g_qkv + (size_t)b * NTOK * QKVN + h * HD;

    // load Q, K, V tiles (float4 over head dim)
#pragma unroll
    for (int l = 0; l < 2; l++) {
        int f = tid + l * 256;       // 0..511
        int t = f >> 3;              // token 0..63
        int d = (f & 7) * 4;         // 0..28
        const float* rp = base + (size_t)t * QKVN;
        float4 q4 = *(const float4*)(rp + 0 * CDIM + d);
        float4 k4 = *(const float4*)(rp + 1 * CDIM + d);
        float4 v4 = *(const float4*)(rp + 2 * CDIM + d);
        Qs[t][d + 0] = q4.x; Qs[t][d + 1] = q4.y; Qs[t][d + 2] = q4.z; Qs[t][d + 3] = q4.w;
        Ks[t][d + 0] = k4.x; Ks[t][d + 1] = k4.y; Ks[t][d + 2] = k4.z; Ks[t][d + 3] = k4.w;
        Vs[t][d + 0] = v4.x; Vs[t][d + 1] = v4.y; Vs[t][d + 2] = v4.z; Vs[t][d + 3] = v4.w;
    }
    __syncthreads();

    // cosine normalization of Q and K rows (eps = 1e-12 on the norm)
    if (tid < 128) {
        float* row = (tid < 64) ? Qs[tid] : Ks[tid - 64];
        float s = 0.f;
#pragma unroll
        for (int d = 0; d < HD; d++) s += row[d] * row[d];
        float inv = 1.0f / fmaxf(sqrtf(s), 1e-12f);
#pragma unroll
        for (int d = 0; d < HD; d++) row[d] *= inv;
    }
    __syncthreads();

    // S = scale * Qn Kn^T + bias + mask ; 4x4 register tile per thread
    {
        const int tx = tid & 15;
        const int ty = tid >> 4;
        const float sc = g_scale[h];
        const float* bi = g_bias + h * NTOK * NTOK;
        const float* mk = mask + (size_t)w * NTOK * NTOK;
        float s4[4][4];
#pragma unroll
        for (int i = 0; i < 4; i++)
#pragma unroll
            for (int j = 0; j < 4; j++) s4[i][j] = 0.f;
#pragma unroll
        for (int d = 0; d < HD; d++) {
            float qa[4], kb[4];
#pragma unroll
            for (int i = 0; i < 4; i++) qa[i] = Qs[ty * 4 + i][d];
#pragma unroll
            for (int j = 0; j < 4; j++) kb[j] = Ks[tx * 4 + j][d];
#pragma unroll
            for (int i = 0; i < 4; i++)
#pragma unroll
                for (int j = 0; j < 4; j++) s4[i][j] += qa[i] * kb[j];
        }
#pragma unroll
        for (int i = 0; i < 4; i++) {
            int r = ty * 4 + i;
#pragma unroll
            for (int j = 0; j < 4; j++) {
                int c = tx * 4 + j;
                Ss[r][c] = s4[i][j] * sc + bi[r * 64 + c] + mk[r * 64 + c];
            }
        }
    }
    __syncthreads();

    // row softmax: 8 warps x 8 rows, 2 cols per lane
    {
        const int wid  = tid >> 5;
        const int lane = tid & 31;
        for (int r = wid * 8; r < wid * 8 + 8; r++) {
            float v0 = Ss[r][lane];
            float v1 = Ss[r][lane + 32];
            float m = fmaxf(v0, v1);
#pragma unroll
            for (int off = 16; off > 0; off >>= 1)
                m = fmaxf(m, __shfl_xor_sync(0xffffffffu, m, off));
            float e0 = __expf(v0 - m);
            float e1 = __expf(v1 - m);
            float s = e0 + e1;
#pragma unroll
            for (int off = 16; off > 0; off >>= 1)
                s += __shfl_xor_sync(0xffffffffu, s, off);
            float inv = 1.0f / s;
            Ss[r][lane]      = e0 * inv;
            Ss[r][lane + 32] = e1 * inv;
        }
    }
    __syncthreads();

    // O = P V : thread computes 4 rows x 2 cols
    {
        const int tx = tid & 15;
        const int ty = tid >> 4;
        float o[4][2];
#pragma unroll
        for (int i = 0; i < 4; i++) { o[i][0] = 0.f; o[i][1] = 0.f; }
#pragma unroll 8
        for (int j = 0; j < 64; j++) {
            float v0 = Vs[j][tx * 2 + 0];
            float v1 = Vs[j][tx * 2 + 1];
#pragma unroll
            for (int i = 0; i < 4; i++) {
                float p = Ss[ty * 4 + i][j];
                o[i][0] += p * v0;
                o[i][1] += p * v1;
            }
        }
#pragma unroll
        for (int i = 0; i < 4; i++) {
            int t = ty * 4 + i;
            float* op = out + (size_t)(b * NTOK + t) * CDIM + h * HD + tx * 2;
            op[0] = o[i][0];
            op[1] = o[i][1];
        }
    }
}

// ---------------------------------------------------------------------------
// Launch
// ---------------------------------------------------------------------------
extern "C" void kernel_launch(void* const* d_in, const int* in_sizes, int n_in,
                              void* d_out, int out_size)
{
    const float* x        = (const float*)d_in[0];
    const float* mask     = (const float*)d_in[1];
    const float* qkv_w    = (const float*)d_in[2];
    const float* qkv_b    = (const float*)d_in[3];
    const float* proj_w   = (const float*)d_in[4];
    const float* proj_b   = (const float*)d_in[5];
    const float* t_scale  = (const float*)d_in[6];
    const float* crpb_w1  = (const float*)d_in[7];
    const float* crpb_b1  = (const float*)d_in[8];
    const float* crpb_w2  = (const float*)d_in[9];
    const float* ctable   = (const float*)d_in[10];
    const int*   rel_idx  = (const int*)d_in[11];
    float*       out      = (float*)d_out;

    float* qkv = nullptr;
    float* att = nullptr;
    cudaGetSymbolAddress((void**)&qkv, g_qkv);
    cudaGetSymbolAddress((void**)&att, g_att);

    // 1. CRPB table + scale, bias fill
    crpb_tbl_kernel<<<1, 256>>>(ctable, crpb_w1, crpb_b1, crpb_w2, t_scale);
    bias_fill_kernel<<<(HEADS * NTOK * NTOK + 255) / 256, 256>>>(rel_idx);

    // 2. QKV projection: (100352 x 512) @ (1536 x 512)^T -> (100352 x 1536)
    {
        dim3 grid(QKVN / BN, MTOT / BM);
        gemm_abT_kernel<<<grid, 256>>>(x, qkv_w, qkv_b, qkv, MTOT, QKVN, CDIM);
    }

    // 3. attention: one block per (window, head)
    attn_kernel<<<BATCH * HEADS, 256>>>(mask, att);

    // 4. output projection: (100352 x 512) @ (512 x 512)^T -> d_out
    {
        dim3 grid(CDIM / BN, MTOT / BM);
        gemm_abT_kernel<<<grid, 256>>>(att, proj_w, proj_b, out, MTOT, CDIM, CDIM);
    }
}

// round 4
// speedup vs baseline: 1.5377x; 1.5377x over previous
#include <cuda_runtime.h>
#include <cstdint>

// ---------------------------------------------------------------------------
// Problem constants
// ---------------------------------------------------------------------------
#define BATCH   1568
#define NTOK    64
#define CDIM    512
#define HEADS   16
#define HD      32
#define NW      49
#define MTOT    (BATCH * NTOK)          // 100352
#define QKVN    (3 * CDIM)              // 1536

// ---------------------------------------------------------------------------
// Device scratch (static globals: allocation-free per harness rules)
// ---------------------------------------------------------------------------
__device__ float g_qkv[(size_t)MTOT * QKVN];    // 616 MB: qkv projection output
__device__ float g_att[(size_t)MTOT * CDIM];    // 205 MB: attention output (B,N,C)
__device__ float g_bias[HEADS * NTOK * NTOK];   // (16,64,64) CRPB bias
__device__ float g_tbl[225 * HEADS];            // CRPB table (2W-1)^2 x H
__device__ float g_scale[HEADS];                // clamped temperature per head

// ---------------------------------------------------------------------------
// tf32 helpers
// ---------------------------------------------------------------------------
__device__ __forceinline__ uint32_t f2tf32(float x) {
    uint32_t r;
    asm("cvt.rna.tf32.f32 %0, %1;" : "=r"(r) : "f"(x));
    return r;
}

__device__ __forceinline__ void mma_tf32(float* c, const uint32_t* a, const uint32_t* b) {
    asm volatile(
        "mma.sync.aligned.m16n8k8.row.col.f32.tf32.tf32.f32 "
        "{%0,%1,%2,%3}, {%4,%5,%6,%7}, {%8,%9}, {%0,%1,%2,%3};"
        : "+f"(c[0]), "+f"(c[1]), "+f"(c[2]), "+f"(c[3])
        : "r"(a[0]), "r"(a[1]), "r"(a[2]), "r"(a[3]),
          "r"(b[0]), "r"(b[1]));
}

// ---------------------------------------------------------------------------
// Kernel 1a: CRPB MLP table + temperature scale
// ---------------------------------------------------------------------------
__global__ void crpb_tbl_kernel(const float* __restrict__ ct,
                                const float* __restrict__ w1,
                                const float* __restrict__ b1,
                                const float* __restrict__ w2,
                                const float* __restrict__ ts)
{
    int e = threadIdx.x;
    if (e < HEADS) {
        g_scale[e] = expf(fminf(ts[e], 4.6051701859880913680f));
    }
    if (e < 225) {
        float c0 = ct[e * 2 + 0];
        float c1 = ct[e * 2 + 1];
        float acc[HEADS];
#pragma unroll
        for (int h = 0; h < HEADS; h++) acc[h] = 0.f;
        for (int j = 0; j < 384; j++) {
            float hv = fmaxf(w1[j * 2 + 0] * c0 + w1[j * 2 + 1] * c1 + b1[j], 0.f);
#pragma unroll
            for (int h = 0; h < HEADS; h++) acc[h] += w2[h * 384 + j] * hv;
        }
#pragma unroll
        for (int h = 0; h < HEADS; h++) g_tbl[e * HEADS + h] = acc[h];
    }
}

// ---------------------------------------------------------------------------
// Kernel 1b: bias[h][i][j] = 16*sigmoid(tbl[rel_index[i][j]][h])
// ---------------------------------------------------------------------------
__global__ void bias_fill_kernel(const int* __restrict__ ridx)
{
    int t = blockIdx.x * blockDim.x + threadIdx.x;
    if (t >= HEADS * NTOK * NTOK) return;
    int h  = t >> 12;
    int ij = t & 4095;
    float v = g_tbl[ridx[ij] * HEADS + h];
    g_bias[t] = 16.f / (1.f + __expf(-v));
}

// ---------------------------------------------------------------------------
// Kernel 2/4: tf32 tensor-core GEMM  C[m][n] = sum_k A[m][k]*B[n][k] + bias[n]
// A: MxK row-major, B: NxK row-major (C = A @ B^T).
// Block tile 128x128, K-tile 32, 256 threads = 8 warps (2m x 4n),
// warp tile 64x32 via m16n8k8 tf32 mma.sync (4x4 mma tiles).
// M % 128 == 0, N % 128 == 0, K % 32 == 0.
// ---------------------------------------------------------------------------
#define BM 128
#define BN 128
#define BKT 32

__global__ __launch_bounds__(256, 2)
void gemm_tf32_abT(const float* __restrict__ A, const float* __restrict__ B,
                   const float* __restrict__ bias, float* __restrict__ C,
                   int M, int N, int K)
{
    // [k][m] layout, pad=8 so fragment reads hit banks 8*(lane%4)+(lane/4): conflict-free
    __shared__ uint32_t As[BKT][BM + 8];
    __shared__ uint32_t Bs[BKT][BN + 8];

    const int tid  = threadIdx.x;
    const int bm   = blockIdx.y * BM;
    const int bn   = blockIdx.x * BN;
    const int warp = tid >> 5;
    const int lane = tid & 31;
    const int wm   = (warp & 1) * 64;   // warp m offset
    const int wn   = (warp >> 1) * 32;  // warp n offset
    const int g    = lane >> 2;         // group id (0..7)
    const int t4   = lane & 3;          // thread in group (0..3)

    float acc[4][4][4];
#pragma unroll
    for (int im = 0; im < 4; im++)
#pragma unroll
        for (int in = 0; in < 4; in++)
#pragma unroll
            for (int r = 0; r < 4; r++) acc[im][in][r] = 0.f;

    for (int k0 = 0; k0 < K; k0 += BKT) {
        // global -> smem with fp32->tf32 rounding.
        // row = f & 127 (lane-consecutive => conflict-free smem stores)
#pragma unroll
        for (int l = 0; l < 4; l++) {
            int f   = tid + l * 256;          // 0..1023
            int row = f & 127;
            int kv  = (f >> 7) * 4;           // 0,4,...,28
            float4 va = *(const float4*)(A + (size_t)(bm + row) * K + k0 + kv);
            As[kv + 0][row] = f2tf32(va.x);
            As[kv + 1][row] = f2tf32(va.y);
            As[kv + 2][row] = f2tf32(va.z);
            As[kv + 3][row] = f2tf32(va.w);
            float4 vb = *(const float4*)(B + (size_t)(bn + row) * K + k0 + kv);
            Bs[kv + 0][row] = f2tf32(vb.x);
            Bs[kv + 1][row] = f2tf32(vb.y);
            Bs[kv + 2][row] = f2tf32(vb.z);
            Bs[kv + 3][row] = f2tf32(vb.w);
        }
        __syncthreads();

#pragma unroll
        for (int kk = 0; kk < BKT; kk += 8) {
            uint32_t af[4][4];
#pragma unroll
            for (int im = 0; im < 4; im++) {
                int r = wm + im * 16 + g;
                af[im][0] = As[kk + t4    ][r    ];
                af[im][1] = As[kk + t4    ][r + 8];
                af[im][2] = As[kk + t4 + 4][r    ];
                af[im][3] = As[kk + t4 + 4][r + 8];
            }
            uint32_t bf[4][2];
#pragma unroll
            for (int in = 0; in < 4; in++) {
                int c = wn + in * 8 + g;
                bf[in][0] = Bs[kk + t4    ][c];
                bf[in][1] = Bs[kk + t4 + 4][c];
            }
#pragma unroll
            for (int im = 0; im < 4; im++)
#pragma unroll
                for (int in = 0; in < 4; in++)
                    mma_tf32(acc[im][in], af[im], bf[in]);
        }
        __syncthreads();
    }

    // epilogue: c0 at (r, c), c1 at (r, c+1), c2 at (r+8, c), c3 at (r+8, c+1)
#pragma unroll
    for (int im = 0; im < 4; im++) {
#pragma unroll
        for (int in = 0; in < 4; in++) {
            int r = bm + wm + im * 16 + g;
            int c = bn + wn + in * 8 + t4 * 2;
            float b0 = bias[c];
            float b1 = bias[c + 1];
            float2 o0 = make_float2(acc[im][in][0] + b0, acc[im][in][1] + b1);
            float2 o1 = make_float2(acc[im][in][2] + b0, acc[im][in][3] + b1);
            *(float2*)(C + (size_t)r * N + c)       = o0;
            *(float2*)(C + (size_t)(r + 8) * N + c) = o1;
        }
    }
}

// ---------------------------------------------------------------------------
// Kernel 3: attention. One block per (window b, head h). (unchanged)
// ---------------------------------------------------------------------------
__global__ __launch_bounds__(256, 4)
void attn_kernel(const float* __restrict__ mask, float* __restrict__ out)
{
    const int bh = blockIdx.x;
    const int b  = bh >> 4;
    const int h  = bh & 15;
    const int w  = b % NW;

    __shared__ float Qs[64][33];
    __shared__ float Ks[64][33];
    __shared__ float Vs[64][33];
    __shared__ float Ss[64][65];

    const int tid = threadIdx.x;
    const float* base = g_qkv + (size_t)b * NTOK * QKVN + h * HD;

#pragma unroll
    for (int l = 0; l < 2; l++) {
        int f = tid + l * 256;
        int t = f >> 3;
        int d = (f & 7) * 4;
        const float* rp = base + (size_t)t * QKVN;
        float4 q4 = *(const float4*)(rp + 0 * CDIM + d);
        float4 k4 = *(const float4*)(rp + 1 * CDIM + d);
        float4 v4 = *(const float4*)(rp + 2 * CDIM + d);
        Qs[t][d + 0] = q4.x; Qs[t][d + 1] = q4.y; Qs[t][d + 2] = q4.z; Qs[t][d + 3] = q4.w;
        Ks[t][d + 0] = k4.x; Ks[t][d + 1] = k4.y; Ks[t][d + 2] = k4.z; Ks[t][d + 3] = k4.w;
        Vs[t][d + 0] = v4.x; Vs[t][d + 1] = v4.y; Vs[t][d + 2] = v4.z; Vs[t][d + 3] = v4.w;
    }
    __syncthreads();

    if (tid < 128) {
        float* row = (tid < 64) ? Qs[tid] : Ks[tid - 64];
        float s = 0.f;
#pragma unroll
        for (int d = 0; d < HD; d++) s += row[d] * row[d];
        float inv = 1.0f / fmaxf(sqrtf(s), 1e-12f);
#pragma unroll
        for (int d = 0; d < HD; d++) row[d] *= inv;
    }
    __syncthreads();

    {
        const int tx = tid & 15;
        const int ty = tid >> 4;
        const float sc = g_scale[h];
        const float* bi = g_bias + h * NTOK * NTOK;
        const float* mk = mask + (size_t)w * NTOK * NTOK;
        float s4[4][4];
#pragma unroll
        for (int i = 0; i < 4; i++)
#pragma unroll
            for (int j = 0; j < 4; j++) s4[i][j] = 0.f;
#pragma unroll
        for (int d = 0; d < HD; d++) {
            float qa[4], kb[4];
#pragma unroll
            for (int i = 0; i < 4; i++) qa[i] = Qs[ty * 4 + i][d];
#pragma unroll
            for (int j = 0; j < 4; j++) kb[j] = Ks[tx * 4 + j][d];
#pragma unroll
            for (int i = 0; i < 4; i++)
#pragma unroll
                for (int j = 0; j < 4; j++) s4[i][j] += qa[i] * kb[j];
        }
#pragma unroll
        for (int i = 0; i < 4; i++) {
            int r = ty * 4 + i;
#pragma unroll
            for (int j = 0; j < 4; j++) {
                int c = tx * 4 + j;
                Ss[r][c] = s4[i][j] * sc + bi[r * 64 + c] + mk[r * 64 + c];
            }
        }
    }
    __syncthreads();

    {
        const int wid  = tid >> 5;
        const int lane = tid & 31;
        for (int r = wid * 8; r < wid * 8 + 8; r++) {
            float v0 = Ss[r][lane];
            float v1 = Ss[r][lane + 32];
            float m = fmaxf(v0, v1);
#pragma unroll
            for (int off = 16; off > 0; off >>= 1)
                m = fmaxf(m, __shfl_xor_sync(0xffffffffu, m, off));
            float e0 = __expf(v0 - m);
            float e1 = __expf(v1 - m);
            float s = e0 + e1;
#pragma unroll
            for (int off = 16; off > 0; off >>= 1)
                s += __shfl_xor_sync(0xffffffffu, s, off);
            float inv = 1.0f / s;
            Ss[r][lane]      = e0 * inv;
            Ss[r][lane + 32] = e1 * inv;
        }
    }
    __syncthreads();

    {
        const int tx = tid & 15;
        const int ty = tid >> 4;
        float o[4][2];
#pragma unroll
        for (int i = 0; i < 4; i++) { o[i][0] = 0.f; o[i][1] = 0.f; }
#pragma unroll 8
        for (int j = 0; j < 64; j++) {
            float v0 = Vs[j][tx * 2 + 0];
            float v1 = Vs[j][tx * 2 + 1];
#pragma unroll
            for (int i = 0; i < 4; i++) {
                float p = Ss[ty * 4 + i][j];
                o[i][0] += p * v0;
                o[i][1] += p * v1;
            }
        }
#pragma unroll
        for (int i = 0; i < 4; i++) {
            int t = ty * 4 + i;
            float* op = out + (size_t)(b * NTOK + t) * CDIM + h * HD + tx * 2;
            op[0] = o[i][0];
            op[1] = o[i][1];
        }
    }
}

// ---------------------------------------------------------------------------
// Launch
// ---------------------------------------------------------------------------
extern "C" void kernel_launch(void* const* d_in, const int* in_sizes, int n_in,
                              void* d_out, int out_size)
{
    const float* x        = (const float*)d_in[0];
    const float* mask     = (const float*)d_in[1];
    const float* qkv_w    = (const float*)d_in[2];
    const float* qkv_b    = (const float*)d_in[3];
    const float* proj_w   = (const float*)d_in[4];
    const float* proj_b   = (const float*)d_in[5];
    const float* t_scale  = (const float*)d_in[6];
    const float* crpb_w1  = (const float*)d_in[7];
    const float* crpb_b1  = (const float*)d_in[8];
    const float* crpb_w2  = (const float*)d_in[9];
    const float* ctable   = (const float*)d_in[10];
    const int*   rel_idx  = (const int*)d_in[11];
    float*       out      = (float*)d_out;

    float* qkv = nullptr;
    float* att = nullptr;
    cudaGetSymbolAddress((void**)&qkv, g_qkv);
    cudaGetSymbolAddress((void**)&att, g_att);

    // 1. CRPB table + scale, bias fill
    crpb_tbl_kernel<<<1, 256>>>(ctable, crpb_w1, crpb_b1, crpb_w2, t_scale);
    bias_fill_kernel<<<(HEADS * NTOK * NTOK + 255) / 256, 256>>>(rel_idx);

    // 2. QKV projection: (100352 x 512) @ (1536 x 512)^T -> (100352 x 1536)
    {
        dim3 grid(QKVN / BN, MTOT / BM);
        gemm_tf32_abT<<<grid, 256>>>(x, qkv_w, qkv_b, qkv, MTOT, QKVN, CDIM);
    }

    // 3. attention: one block per (window, head)
    attn_kernel<<<BATCH * HEADS, 256>>>(mask, att);

    // 4. output projection: (100352 x 512) @ (512 x 512)^T -> d_out
    {
        dim3 grid(CDIM / BN, MTOT / BM);
        gemm_tf32_abT<<<grid, 256>>>(att, proj_w, proj_b, out, MTOT, CDIM, CDIM);
    }
}

// round 5
// speedup vs baseline: 2.6088x; 1.6966x over previous
#include <cuda_runtime.h>
#include <cstdint>

// ---------------------------------------------------------------------------
// Problem constants
// ---------------------------------------------------------------------------
#define BATCH   1568
#define NTOK    64
#define CDIM    512
#define HEADS   16
#define HD      32
#define NW      49
#define MTOT    (BATCH * NTOK)          // 100352
#define QKVN    (3 * CDIM)              // 1536

// ---------------------------------------------------------------------------
// Device scratch (static globals: allocation-free per harness rules)
// ---------------------------------------------------------------------------
__device__ float g_qkv[(size_t)MTOT * QKVN];    // qkv projection output
__device__ float g_att[(size_t)MTOT * CDIM];    // attention output (B,N,C)
__device__ float g_bias[HEADS * NTOK * NTOK];   // (16,64,64) CRPB bias
__device__ float g_tbl[225 * HEADS];            // CRPB table
__device__ float g_scale[HEADS];                // clamped temperature per head

// ---------------------------------------------------------------------------
// tf32 / mma helpers
// ---------------------------------------------------------------------------
__device__ __forceinline__ uint32_t f2tf32(float x) {
    uint32_t r;
    asm("cvt.rna.tf32.f32 %0, %1;" : "=r"(r) : "f"(x));
    return r;
}

__device__ __forceinline__ void mma_tf32(float* c, const uint32_t* a, const uint32_t* b) {
    asm volatile(
        "mma.sync.aligned.m16n8k8.row.col.f32.tf32.tf32.f32 "
        "{%0,%1,%2,%3}, {%4,%5,%6,%7}, {%8,%9}, {%0,%1,%2,%3};"
        : "+f"(c[0]), "+f"(c[1]), "+f"(c[2]), "+f"(c[3])
        : "r"(a[0]), "r"(a[1]), "r"(a[2]), "r"(a[3]),
          "r"(b[0]), "r"(b[1]));
}

__device__ __forceinline__ void ldsm_x4(uint32_t* r, const uint32_t* p) {
    uint32_t addr = (uint32_t)__cvta_generic_to_shared(p);
    asm volatile("ldmatrix.sync.aligned.m8n8.x4.shared.b16 {%0,%1,%2,%3}, [%4];"
                 : "=r"(r[0]), "=r"(r[1]), "=r"(r[2]), "=r"(r[3]) : "r"(addr));
}

// ---------------------------------------------------------------------------
// Kernel 1a: CRPB MLP table + temperature scale
// ---------------------------------------------------------------------------
__global__ void crpb_tbl_kernel(const float* __restrict__ ct,
                                const float* __restrict__ w1,
                                const float* __restrict__ b1,
                                const float* __restrict__ w2,
                                const float* __restrict__ ts)
{
    int e = threadIdx.x;
    if (e < HEADS) {
        g_scale[e] = expf(fminf(ts[e], 4.6051701859880913680f));
    }
    if (e < 225) {
        float c0 = ct[e * 2 + 0];
        float c1 = ct[e * 2 + 1];
        float acc[HEADS];
#pragma unroll
        for (int h = 0; h < HEADS; h++) acc[h] = 0.f;
        for (int j = 0; j < 384; j++) {
            float hv = fmaxf(w1[j * 2 + 0] * c0 + w1[j * 2 + 1] * c1 + b1[j], 0.f);
#pragma unroll
            for (int h = 0; h < HEADS; h++) acc[h] += w2[h * 384 + j] * hv;
        }
#pragma unroll
        for (int h = 0; h < HEADS; h++) g_tbl[e * HEADS + h] = acc[h];
    }
}

// ---------------------------------------------------------------------------
// Kernel 1b: bias[h][i][j] = 16*sigmoid(tbl[rel_index[i][j]][h])
// ---------------------------------------------------------------------------
__global__ void bias_fill_kernel(const int* __restrict__ ridx)
{
    int t = blockIdx.x * blockDim.x + threadIdx.x;
    if (t >= HEADS * NTOK * NTOK) return;
    int h  = t >> 12;
    int ij = t & 4095;
    float v = g_tbl[ridx[ij] * HEADS + h];
    g_bias[t] = 16.f / (1.f + __expf(-v));
}

// ---------------------------------------------------------------------------
// Kernel 2/4: tf32 tensor-core GEMM  C[m][n] = sum_k A[m][k]*B[n][k] + bias[n]
// A: MxK row-major, B: NxK row-major (C = A @ B^T).
// Block tile 128x128, K-tile 32, 256 threads = 8 warps (2m x 4n),
// warp tile 64x32 via m16n8k8 tf32 mma.sync.
// Smem [row][k] with XOR-16B swizzle, ldmatrix.x4 fragment loads,
// 2-stage smem double buffering with register prefetch of the next tile.
// M % 128 == 0, N % 128 == 0, K % 32 == 0.
// ---------------------------------------------------------------------------
#define BM 128
#define BN 128
#define BKT 32
#define GEMM_SMEM (2 * (BM + BN) * BKT * 4)   // 65536 bytes

__global__ __launch_bounds__(256, 2)
void gemm_tf32_abT(const float* __restrict__ A, const float* __restrict__ B,
                   const float* __restrict__ bias, float* __restrict__ C,
                   int M, int N, int K)
{
    extern __shared__ uint32_t sm[];
    uint32_t* AsBase = sm;                     // [2][BM][BKT]
    uint32_t* BsBase = sm + 2 * BM * BKT;      // [2][BN][BKT]

    const int tid  = threadIdx.x;
    const int bm   = blockIdx.y * BM;
    const int bn   = blockIdx.x * BN;
    const int warp = tid >> 5;
    const int lane = tid & 31;
    const int wm   = (warp & 1) * 64;
    const int wn   = (warp >> 1) * 32;
    const int g    = lane >> 2;
    const int t4   = lane & 3;

    // ldmatrix per-lane address decomposition
    const int lt = lane >> 3;      // tile index 0..3
    const int lr = lane & 7;       // row within tile
    // A tiles: t0=(rows 0-7,k 0-3) t1=(rows 8-15,k 0-3) t2=(rows 0-7,k 4-7) t3=(rows 8-15,k 4-7)
    const int a_row_l = wm + (lt & 1) * 8 + lr;   // + im*16
    const int a_chk_l = lt >> 1;                  // + kk/4
    // B tiles: t0=(n 0-7,k 0-3) t1=(n 0-7,k 4-7) t2=(n 8-15,k 0-3) t3=(n 8-15,k 4-7)
    const int b_row_l = wn + (lt >> 1) * 8 + lr;  // + inp*16
    const int b_chk_l = lt & 1;                   // + kk/4

    // global load assignment: 8 threads per row, fixed 16B chunk per thread
    const int row0   = tid >> 3;     // rows row0, row0+32, row0+64, row0+96
    const int lchunk = tid & 7;

    float acc[4][4][4];
#pragma unroll
    for (int im = 0; im < 4; im++)
#pragma unroll
        for (int in = 0; in < 4; in++)
#pragma unroll
            for (int r = 0; r < 4; r++) acc[im][in][r] = 0.f;

    const int NIT = K / BKT;
    float4 va[4], vb[4];

    // prologue: load tile 0
#pragma unroll
    for (int l = 0; l < 4; l++) {
        int row = row0 + 32 * l;
        va[l] = *(const float4*)(A + (size_t)(bm + row) * K + lchunk * 4);
        vb[l] = *(const float4*)(B + (size_t)(bn + row) * K + lchunk * 4);
    }
    // cvt + store stage 0
#pragma unroll
    for (int l = 0; l < 4; l++) {
        int row = row0 + 32 * l;
        int sc  = (lchunk ^ (row & 7)) << 2;
        uint32_t* ap = AsBase + row * BKT + sc;
        ap[0] = f2tf32(va[l].x); ap[1] = f2tf32(va[l].y);
        ap[2] = f2tf32(va[l].z); ap[3] = f2tf32(va[l].w);
        uint32_t* bp = BsBase + row * BKT + sc;
        bp[0] = f2tf32(vb[l].x); bp[1] = f2tf32(vb[l].y);
        bp[2] = f2tf32(vb[l].z); bp[3] = f2tf32(vb[l].w);
    }
    __syncthreads();

    for (int it = 0; it < NIT; it++) {
        const int s = it & 1;
        // prefetch next tile into registers
        if (it + 1 < NIT) {
            int koff = (it + 1) * BKT + lchunk * 4;
#pragma unroll
            for (int l = 0; l < 4; l++) {
                int row = row0 + 32 * l;
                va[l] = *(const float4*)(A + (size_t)(bm + row) * K + koff);
                vb[l] = *(const float4*)(B + (size_t)(bn + row) * K + koff);
            }
        }

        // compute from stage s
        const uint32_t* Ast = AsBase + s * BM * BKT;
        const uint32_t* Bst = BsBase + s * BN * BKT;
#pragma unroll
        for (int kk = 0; kk < BKT; kk += 8) {
            const int kc = kk >> 2;
            uint32_t af[4][4];
#pragma unroll
            for (int im = 0; im < 4; im++) {
                int row = a_row_l + im * 16;
                int chk = kc + a_chk_l;
                ldsm_x4(af[im], Ast + row * BKT + ((chk ^ (row & 7)) << 2));
            }
            uint32_t bfr[8];
#pragma unroll
            for (int inp = 0; inp < 2; inp++) {
                int row = b_row_l + inp * 16;
                int chk = kc + b_chk_l;
                ldsm_x4(bfr + inp * 4, Bst + row * BKT + ((chk ^ (row & 7)) << 2));
            }
#pragma unroll
            for (int im = 0; im < 4; im++)
#pragma unroll
                for (int in = 0; in < 4; in++)
                    mma_tf32(acc[im][in], af[im], bfr + in * 2);
        }

        // store next tile into stage s^1
        if (it + 1 < NIT) {
            uint32_t* Asn = AsBase + (s ^ 1) * BM * BKT;
            uint32_t* Bsn = BsBase + (s ^ 1) * BN * BKT;
#pragma unroll
            for (int l = 0; l < 4; l++) {
                int row = row0 + 32 * l;
                int sc  = (lchunk ^ (row & 7)) << 2;
                uint32_t* ap = Asn + row * BKT + sc;
                ap[0] = f2tf32(va[l].x); ap[1] = f2tf32(va[l].y);
                ap[2] = f2tf32(va[l].z); ap[3] = f2tf32(va[l].w);
                uint32_t* bp = Bsn + row * BKT + sc;
                bp[0] = f2tf32(vb[l].x); bp[1] = f2tf32(vb[l].y);
                bp[2] = f2tf32(vb[l].z); bp[3] = f2tf32(vb[l].w);
            }
        }
        __syncthreads();
    }

    // epilogue
#pragma unroll
    for (int im = 0; im < 4; im++) {
#pragma unroll
        for (int in = 0; in < 4; in++) {
            int r = bm + wm + im * 16 + g;
            int c = bn + wn + in * 8 + t4 * 2;
            float b0 = bias[c];
            float b1 = bias[c + 1];
            float2 o0 = make_float2(acc[im][in][0] + b0, acc[im][in][1] + b1);
            float2 o1 = make_float2(acc[im][in][2] + b0, acc[im][in][3] + b1);
            *(float2*)(C + (size_t)r * N + c)       = o0;
            *(float2*)(C + (size_t)(r + 8) * N + c) = o1;
        }
    }
}

// ---------------------------------------------------------------------------
// Kernel 3: attention. One block per (window b, head h). (unchanged)
// ---------------------------------------------------------------------------
__global__ __launch_bounds__(256, 4)
void attn_kernel(const float* __restrict__ mask, float* __restrict__ out)
{
    const int bh = blockIdx.x;
    const int b  = bh >> 4;
    const int h  = bh & 15;
    const int w  = b % NW;

    __shared__ float Qs[64][33];
    __shared__ float Ks[64][33];
    __shared__ float Vs[64][33];
    __shared__ float Ss[64][65];

    const int tid = threadIdx.x;
    const float* base = g_qkv + (size_t)b * NTOK * QKVN + h * HD;

#pragma unroll
    for (int l = 0; l < 2; l++) {
        int f = tid + l * 256;
        int t = f >> 3;
        int d = (f & 7) * 4;
        const float* rp = base + (size_t)t * QKVN;
        float4 q4 = *(const float4*)(rp + 0 * CDIM + d);
        float4 k4 = *(const float4*)(rp + 1 * CDIM + d);
        float4 v4 = *(const float4*)(rp + 2 * CDIM + d);
        Qs[t][d + 0] = q4.x; Qs[t][d + 1] = q4.y; Qs[t][d + 2] = q4.z; Qs[t][d + 3] = q4.w;
        Ks[t][d + 0] = k4.x; Ks[t][d + 1] = k4.y; Ks[t][d + 2] = k4.z; Ks[t][d + 3] = k4.w;
        Vs[t][d + 0] = v4.x; Vs[t][d + 1] = v4.y; Vs[t][d + 2] = v4.z; Vs[t][d + 3] = v4.w;
    }
    __syncthreads();

    if (tid < 128) {
        float* row = (tid < 64) ? Qs[tid] : Ks[tid - 64];
        float s = 0.f;
#pragma unroll
        for (int d = 0; d < HD; d++) s += row[d] * row[d];
        float inv = 1.0f / fmaxf(sqrtf(s), 1e-12f);
#pragma unroll
        for (int d = 0; d < HD; d++) row[d] *= inv;
    }
    __syncthreads();

    {
        const int tx = tid & 15;
        const int ty = tid >> 4;
        const float sc = g_scale[h];
        const float* bi = g_bias + h * NTOK * NTOK;
        const float* mk = mask + (size_t)w * NTOK * NTOK;
        float s4[4][4];
#pragma unroll
        for (int i = 0; i < 4; i++)
#pragma unroll
            for (int j = 0; j < 4; j++) s4[i][j] = 0.f;
#pragma unroll
        for (int d = 0; d < HD; d++) {
            float qa[4], kb[4];
#pragma unroll
            for (int i = 0; i < 4; i++) qa[i] = Qs[ty * 4 + i][d];
#pragma unroll
            for (int j = 0; j < 4; j++) kb[j] = Ks[tx * 4 + j][d];
#pragma unroll
            for (int i = 0; i < 4; i++)
#pragma unroll
                for (int j = 0; j < 4; j++) s4[i][j] += qa[i] * kb[j];
        }
#pragma unroll
        for (int i = 0; i < 4; i++) {
            int r = ty * 4 + i;
#pragma unroll
            for (int j = 0; j < 4; j++) {
                int c = tx * 4 + j;
                Ss[r][c] = s4[i][j] * sc + bi[r * 64 + c] + mk[r * 64 + c];
            }
        }
    }
    __syncthreads();

    {
        const int wid  = tid >> 5;
        const int lane = tid & 31;
        for (int r = wid * 8; r < wid * 8 + 8; r++) {
            float v0 = Ss[r][lane];
            float v1 = Ss[r][lane + 32];
            float m = fmaxf(v0, v1);
#pragma unroll
            for (int off = 16; off > 0; off >>= 1)
                m = fmaxf(m, __shfl_xor_sync(0xffffffffu, m, off));
            float e0 = __expf(v0 - m);
            float e1 = __expf(v1 - m);
            float s = e0 + e1;
#pragma unroll
            for (int off = 16; off > 0; off >>= 1)
                s += __shfl_xor_sync(0xffffffffu, s, off);
            float inv = 1.0f / s;
            Ss[r][lane]      = e0 * inv;
            Ss[r][lane + 32] = e1 * inv;
        }
    }
    __syncthreads();

    {
        const int tx = tid & 15;
        const int ty = tid >> 4;
        float o[4][2];
#pragma unroll
        for (int i = 0; i < 4; i++) { o[i][0] = 0.f; o[i][1] = 0.f; }
#pragma unroll 8
        for (int j = 0; j < 64; j++) {
            float v0 = Vs[j][tx * 2 + 0];
            float v1 = Vs[j][tx * 2 + 1];
#pragma unroll
            for (int i = 0; i < 4; i++) {
                float p = Ss[ty * 4 + i][j];
                o[i][0] += p * v0;
                o[i][1] += p * v1;
            }
        }
#pragma unroll
        for (int i = 0; i < 4; i++) {
            int t = ty * 4 + i;
            float* op = out + (size_t)(b * NTOK + t) * CDIM + h * HD + tx * 2;
            op[0] = o[i][0];
            op[1] = o[i][1];
        }
    }
}

// ---------------------------------------------------------------------------
// Launch
// ---------------------------------------------------------------------------
extern "C" void kernel_launch(void* const* d_in, const int* in_sizes, int n_in,
                              void* d_out, int out_size)
{
    const float* x        = (const float*)d_in[0];
    const float* mask     = (const float*)d_in[1];
    const float* qkv_w    = (const float*)d_in[2];
    const float* qkv_b    = (const float*)d_in[3];
    const float* proj_w   = (const float*)d_in[4];
    const float* proj_b   = (const float*)d_in[5];
    const float* t_scale  = (const float*)d_in[6];
    const float* crpb_w1  = (const float*)d_in[7];
    const float* crpb_b1  = (const float*)d_in[8];
    const float* crpb_w2  = (const float*)d_in[9];
    const float* ctable   = (const float*)d_in[10];
    const int*   rel_idx  = (const int*)d_in[11];
    float*       out      = (float*)d_out;

    float* qkv = nullptr;
    float* att = nullptr;
    cudaGetSymbolAddress((void**)&qkv, g_qkv);
    cudaGetSymbolAddress((void**)&att, g_att);

    static bool attr_set = false;
    if (!attr_set) {
        cudaFuncSetAttribute(gemm_tf32_abT,
                             cudaFuncAttributeMaxDynamicSharedMemorySize, GEMM_SMEM);
        attr_set = true;
    }

    // 1. CRPB table + scale, bias fill
    crpb_tbl_kernel<<<1, 256>>>(ctable, crpb_w1, crpb_b1, crpb_w2, t_scale);
    bias_fill_kernel<<<(HEADS * NTOK * NTOK + 255) / 256, 256>>>(rel_idx);

    // 2. QKV projection: (100352 x 512) @ (1536 x 512)^T -> (100352 x 1536)
    {
        dim3 grid(QKVN / BN, MTOT / BM);
        gemm_tf32_abT<<<grid, 256, GEMM_SMEM>>>(x, qkv_w, qkv_b, qkv, MTOT, QKVN, CDIM);
    }

    // 3. attention: one block per (window, head)
    attn_kernel<<<BATCH * HEADS, 256>>>(mask, att);

    // 4. output projection: (100352 x 512) @ (512 x 512)^T -> d_out
    {
        dim3 grid(CDIM / BN, MTOT / BM);
        gemm_tf32_abT<<<grid, 256, GEMM_SMEM>>>(att, proj_w, proj_b, out, MTOT, CDIM, CDIM);
    }
}